// round 2
// baseline (speedup 1.0000x reference)
#include <cuda_runtime.h>

#define DM 512
#define NH 8
#define DK 64
#define BB 4
#define LL 2048
#define MROWS (BB*LL)               // 8192
#define OUT_ELEMS ((size_t)MROWS*DM)        // 4,194,304
#define ATTN_ELEMS ((size_t)BB*NH*LL*LL)    // 134,217,728

// Scratch for projected Q/K/V in [B*L, 512] layout (head h at cols h*64..h*64+63)
__device__ float g_Q[MROWS*DM];
__device__ float g_K[MROWS*DM];
__device__ float g_V[MROWS*DM];

// ---------------------------------------------------------------------------
// Projection GEMM: Y[M,512] = X[M,512] @ W[512,512] + b
// BM=BN=64, BK=16, 256 threads, 4x4 microtile
// ---------------------------------------------------------------------------
__global__ void __launch_bounds__(256) proj_kernel(const float* __restrict__ X,
                                                   const float* __restrict__ W,
                                                   const float* __restrict__ bias,
                                                   float* __restrict__ Y)
{
    __shared__ float As[16][64];
    __shared__ float Bs[16][68];
    const int tid = threadIdx.x;
    const int tx = tid & 15, ty = tid >> 4;
    const int bm = blockIdx.y * 64, bn = blockIdx.x * 64;
    const int lm  = tid >> 2;          // 0..63
    const int lk  = (tid & 3) << 2;    // 0,4,8,12
    const int lkr = tid >> 4;          // 0..15
    const int lnq = (tid & 15) << 2;   // 0..60

    float acc[4][4] = {};
    for (int k0 = 0; k0 < 512; k0 += 16) {
        float4 a = *(const float4*)&X[(size_t)(bm + lm) * 512 + k0 + lk];
        As[lk+0][lm] = a.x; As[lk+1][lm] = a.y; As[lk+2][lm] = a.z; As[lk+3][lm] = a.w;
        float4 w4 = *(const float4*)&W[(size_t)(k0 + lkr) * 512 + bn + lnq];
        *(float4*)&Bs[lkr][lnq] = w4;
        __syncthreads();
        #pragma unroll
        for (int k = 0; k < 16; k++) {
            float ar[4], br[4];
            #pragma unroll
            for (int i = 0; i < 4; i++) ar[i] = As[k][ty*4+i];
            #pragma unroll
            for (int j = 0; j < 4; j++) br[j] = Bs[k][tx*4+j];
            #pragma unroll
            for (int i = 0; i < 4; i++)
                #pragma unroll
                for (int j = 0; j < 4; j++)
                    acc[i][j] += ar[i] * br[j];
        }
        __syncthreads();
    }
    #pragma unroll
    for (int i = 0; i < 4; i++) {
        #pragma unroll
        for (int j = 0; j < 4; j++) {
            int n = bn + tx*4 + j;
            Y[(size_t)(bm + ty*4 + i) * 512 + n] = acc[i][j] + bias[n];
        }
    }
}

// ---------------------------------------------------------------------------
// Scores: S[bh] = Q[bh] @ K[bh]^T * (1/8).  M=N=2048, Kdim=64.
// Writes raw scaled scores into attn region.
// ---------------------------------------------------------------------------
__global__ void __launch_bounds__(256) scores_kernel(float* __restrict__ attn)
{
    __shared__ float As[16][64];
    __shared__ float Bs[16][68];
    const int tid = threadIdx.x;
    const int tx = tid & 15, ty = tid >> 4;
    const int bh = blockIdx.z;
    const int b = bh >> 3, h = bh & 7;
    const float* __restrict__ Qp = g_Q + (size_t)b * LL * DM + h * DK;
    const float* __restrict__ Kp = g_K + (size_t)b * LL * DM + h * DK;
    const int bm = blockIdx.y * 64, bn = blockIdx.x * 64;
    const int lm = tid >> 2;
    const int lk = (tid & 3) << 2;

    float acc[4][4] = {};
    for (int k0 = 0; k0 < 64; k0 += 16) {
        float4 a = *(const float4*)&Qp[(size_t)(bm + lm) * DM + k0 + lk];
        As[lk+0][lm] = a.x; As[lk+1][lm] = a.y; As[lk+2][lm] = a.z; As[lk+3][lm] = a.w;
        float4 c = *(const float4*)&Kp[(size_t)(bn + lm) * DM + k0 + lk];
        Bs[lk+0][lm] = c.x; Bs[lk+1][lm] = c.y; Bs[lk+2][lm] = c.z; Bs[lk+3][lm] = c.w;
        __syncthreads();
        #pragma unroll
        for (int k = 0; k < 16; k++) {
            float ar[4], br[4];
            #pragma unroll
            for (int i = 0; i < 4; i++) ar[i] = As[k][ty*4+i];
            #pragma unroll
            for (int j = 0; j < 4; j++) br[j] = Bs[k][tx*4+j];
            #pragma unroll
            for (int i = 0; i < 4; i++)
                #pragma unroll
                for (int j = 0; j < 4; j++)
                    acc[i][j] += ar[i] * br[j];
        }
        __syncthreads();
    }
    float* S = attn + (size_t)bh * LL * LL;
    #pragma unroll
    for (int i = 0; i < 4; i++)
        #pragma unroll
        for (int j = 0; j < 4; j++)
            S[(size_t)(bm + ty*4 + i) * LL + bn + tx*4 + j] = acc[i][j] * 0.125f;
}

// ---------------------------------------------------------------------------
// Row softmax in place.  One block (256 thr) per row of 2048.
// ---------------------------------------------------------------------------
__global__ void __launch_bounds__(256) softmax_kernel(float* __restrict__ attn)
{
    float* row = attn + (size_t)blockIdx.x * LL;
    const int tid = threadIdx.x;
    __shared__ float red[32];

    float4 v0 = *(const float4*)&row[tid * 4];
    float4 v1 = *(const float4*)&row[1024 + tid * 4];
    float m = fmaxf(fmaxf(fmaxf(v0.x, v0.y), fmaxf(v0.z, v0.w)),
                    fmaxf(fmaxf(v1.x, v1.y), fmaxf(v1.z, v1.w)));
    #pragma unroll
    for (int o = 16; o; o >>= 1) m = fmaxf(m, __shfl_xor_sync(0xffffffffu, m, o));
    if ((tid & 31) == 0) red[tid >> 5] = m;
    __syncthreads();
    if (tid < 32) {
        float x = (tid < 8) ? red[tid] : -3.4e38f;
        #pragma unroll
        for (int o = 4; o; o >>= 1) x = fmaxf(x, __shfl_xor_sync(0xffffffffu, x, o));
        if (tid == 0) red[0] = x;
    }
    __syncthreads();
    m = red[0];
    __syncthreads();

    float e[8];
    e[0] = __expf(v0.x - m); e[1] = __expf(v0.y - m);
    e[2] = __expf(v0.z - m); e[3] = __expf(v0.w - m);
    e[4] = __expf(v1.x - m); e[5] = __expf(v1.y - m);
    e[6] = __expf(v1.z - m); e[7] = __expf(v1.w - m);
    float s = 0.f;
    #pragma unroll
    for (int i = 0; i < 8; i++) s += e[i];
    #pragma unroll
    for (int o = 16; o; o >>= 1) s += __shfl_xor_sync(0xffffffffu, s, o);
    if ((tid & 31) == 0) red[tid >> 5] = s;
    __syncthreads();
    if (tid < 32) {
        float x = (tid < 8) ? red[tid] : 0.f;
        #pragma unroll
        for (int o = 4; o; o >>= 1) x += __shfl_xor_sync(0xffffffffu, x, o);
        if (tid == 0) red[0] = x;
    }
    __syncthreads();
    float inv = 1.0f / red[0];

    float4 o0 = make_float4(e[0]*inv, e[1]*inv, e[2]*inv, e[3]*inv);
    float4 o1 = make_float4(e[4]*inv, e[5]*inv, e[6]*inv, e[7]*inv);
    *(float4*)&row[tid * 4] = o0;
    *(float4*)&row[1024 + tid * 4] = o1;
}

// ---------------------------------------------------------------------------
// Output: O[bh][2048,64] = P[bh][2048,2048] @ V[bh][2048,64]
// BM=64, BN=64(=DK), BK=16. grid (32 m-tiles, 32 bh).
// ---------------------------------------------------------------------------
__global__ void __launch_bounds__(256) out_kernel(const float* __restrict__ attn,
                                                  float* __restrict__ out)
{
    __shared__ float As[16][64];
    __shared__ float Bs[16][68];
    const int tid = threadIdx.x;
    const int tx = tid & 15, ty = tid >> 4;
    const int bh = blockIdx.y;
    const int b = bh >> 3, h = bh & 7;
    const float* __restrict__ P  = attn + (size_t)bh * LL * LL;
    const float* __restrict__ Vp = g_V + (size_t)b * LL * DM + h * DK;
    const int bm = blockIdx.x * 64;
    const int lm  = tid >> 2;
    const int lk  = (tid & 3) << 2;
    const int lkr = tid >> 4;
    const int lnq = (tid & 15) << 2;

    float acc[4][4] = {};
    for (int k0 = 0; k0 < LL; k0 += 16) {
        float4 a = *(const float4*)&P[(size_t)(bm + lm) * LL + k0 + lk];
        As[lk+0][lm] = a.x; As[lk+1][lm] = a.y; As[lk+2][lm] = a.z; As[lk+3][lm] = a.w;
        float4 v4 = *(const float4*)&Vp[(size_t)(k0 + lkr) * DM + lnq];
        *(float4*)&Bs[lkr][lnq] = v4;
        __syncthreads();
        #pragma unroll
        for (int k = 0; k < 16; k++) {
            float ar[4], br[4];
            #pragma unroll
            for (int i = 0; i < 4; i++) ar[i] = As[k][ty*4+i];
            #pragma unroll
            for (int j = 0; j < 4; j++) br[j] = Bs[k][tx*4+j];
            #pragma unroll
            for (int i = 0; i < 4; i++)
                #pragma unroll
                for (int j = 0; j < 4; j++)
                    acc[i][j] += ar[i] * br[j];
        }
        __syncthreads();
    }
    #pragma unroll
    for (int i = 0; i < 4; i++)
        #pragma unroll
        for (int j = 0; j < 4; j++)
            out[(size_t)(b * LL + bm + ty*4 + i) * DM + h * DK + tx*4 + j] = acc[i][j];
}

// ---------------------------------------------------------------------------
extern "C" void kernel_launch(void* const* d_in, const int* in_sizes, int n_in,
                              void* d_out, int out_size)
{
    const float* q  = (const float*)d_in[0];
    const float* k  = (const float*)d_in[1];
    const float* v  = (const float*)d_in[2];
    const float* Wq = (const float*)d_in[3];
    const float* bq = (const float*)d_in[4];
    const float* Wk = (const float*)d_in[5];
    const float* bk = (const float*)d_in[6];
    const float* Wv = (const float*)d_in[7];
    const float* bv = (const float*)d_in[8];

    float* out  = (float*)d_out;
    float* attn = out + OUT_ELEMS;

    float *gQ, *gK, *gV;
    cudaGetSymbolAddress((void**)&gQ, g_Q);
    cudaGetSymbolAddress((void**)&gK, g_K);
    cudaGetSymbolAddress((void**)&gV, g_V);

    dim3 blk(256);
    proj_kernel<<<dim3(8, 128), blk>>>(q, Wq, bq, gQ);
    proj_kernel<<<dim3(8, 128), blk>>>(k, Wk, bk, gK);
    proj_kernel<<<dim3(8, 128), blk>>>(v, Wv, bv, gV);
    scores_kernel<<<dim3(32, 32, 32), blk>>>(attn);
    softmax_kernel<<<BB * NH * LL, blk>>>(attn);
    out_kernel<<<dim3(32, 32), blk>>>(attn, out);
}

// round 3
// speedup vs baseline: 1.0005x; 1.0005x over previous
#include <cuda_runtime.h>

#define DM 512
#define NH 8
#define DK 64
#define BB 4
#define LL 2048
#define MROWS (BB*LL)               // 8192
#define OUT_ELEMS ((size_t)MROWS*DM)        // 4,194,304
#define ATTN_ELEMS ((size_t)BB*NH*LL*LL)    // 134,217,728

// Scratch for projected Q/K/V in [B*L, 512] layout (head h at cols h*64..h*64+63)
__device__ float g_Q[MROWS*DM];
__device__ float g_K[MROWS*DM];
__device__ float g_V[MROWS*DM];

// ---------------------------------------------------------------------------
// Projection GEMM: Y[M,512] = X[M,512] @ W[512,512] + b
// BM=BN=64, BK=16, 256 threads, 4x4 microtile
// ---------------------------------------------------------------------------
__global__ void __launch_bounds__(256) proj_kernel(const float* __restrict__ X,
                                                   const float* __restrict__ W,
                                                   const float* __restrict__ bias,
                                                   float* __restrict__ Y)
{
    __shared__ float As[16][64];
    __shared__ float Bs[16][68];
    const int tid = threadIdx.x;
    const int tx = tid & 15, ty = tid >> 4;
    const int bm = blockIdx.y * 64, bn = blockIdx.x * 64;
    const int lm  = tid >> 2;          // 0..63
    const int lk  = (tid & 3) << 2;    // 0,4,8,12
    const int lkr = tid >> 4;          // 0..15
    const int lnq = (tid & 15) << 2;   // 0..60

    float acc[4][4] = {};
    for (int k0 = 0; k0 < 512; k0 += 16) {
        float4 a = *(const float4*)&X[(size_t)(bm + lm) * 512 + k0 + lk];
        As[lk+0][lm] = a.x; As[lk+1][lm] = a.y; As[lk+2][lm] = a.z; As[lk+3][lm] = a.w;
        float4 w4 = *(const float4*)&W[(size_t)(k0 + lkr) * 512 + bn + lnq];
        *(float4*)&Bs[lkr][lnq] = w4;
        __syncthreads();
        #pragma unroll
        for (int k = 0; k < 16; k++) {
            float ar[4], br[4];
            #pragma unroll
            for (int i = 0; i < 4; i++) ar[i] = As[k][ty*4+i];
            #pragma unroll
            for (int j = 0; j < 4; j++) br[j] = Bs[k][tx*4+j];
            #pragma unroll
            for (int i = 0; i < 4; i++)
                #pragma unroll
                for (int j = 0; j < 4; j++)
                    acc[i][j] += ar[i] * br[j];
        }
        __syncthreads();
    }
    #pragma unroll
    for (int i = 0; i < 4; i++) {
        #pragma unroll
        for (int j = 0; j < 4; j++) {
            int n = bn + tx*4 + j;
            Y[(size_t)(bm + ty*4 + i) * 512 + n] = acc[i][j] + bias[n];
        }
    }
}

// ---------------------------------------------------------------------------
// Scores: S[bh] = Q[bh] @ K[bh]^T * (1/8).  M=N=2048, Kdim=64.
// Writes raw scaled scores into attn region.
// ---------------------------------------------------------------------------
__global__ void __launch_bounds__(256) scores_kernel(float* __restrict__ attn)
{
    __shared__ float As[16][64];
    __shared__ float Bs[16][68];
    const int tid = threadIdx.x;
    const int tx = tid & 15, ty = tid >> 4;
    const int bh = blockIdx.z;
    const int b = bh >> 3, h = bh & 7;
    const float* __restrict__ Qp = g_Q + (size_t)b * LL * DM + h * DK;
    const float* __restrict__ Kp = g_K + (size_t)b * LL * DM + h * DK;
    const int bm = blockIdx.y * 64, bn = blockIdx.x * 64;
    const int lm = tid >> 2;
    const int lk = (tid & 3) << 2;

    float acc[4][4] = {};
    for (int k0 = 0; k0 < 64; k0 += 16) {
        float4 a = *(const float4*)&Qp[(size_t)(bm + lm) * DM + k0 + lk];
        As[lk+0][lm] = a.x; As[lk+1][lm] = a.y; As[lk+2][lm] = a.z; As[lk+3][lm] = a.w;
        float4 c = *(const float4*)&Kp[(size_t)(bn + lm) * DM + k0 + lk];
        Bs[lk+0][lm] = c.x; Bs[lk+1][lm] = c.y; Bs[lk+2][lm] = c.z; Bs[lk+3][lm] = c.w;
        __syncthreads();
        #pragma unroll
        for (int k = 0; k < 16; k++) {
            float ar[4], br[4];
            #pragma unroll
            for (int i = 0; i < 4; i++) ar[i] = As[k][ty*4+i];
            #pragma unroll
            for (int j = 0; j < 4; j++) br[j] = Bs[k][tx*4+j];
            #pragma unroll
            for (int i = 0; i < 4; i++)
                #pragma unroll
                for (int j = 0; j < 4; j++)
                    acc[i][j] += ar[i] * br[j];
        }
        __syncthreads();
    }
    float* S = attn + (size_t)bh * LL * LL;
    #pragma unroll
    for (int i = 0; i < 4; i++)
        #pragma unroll
        for (int j = 0; j < 4; j++)
            S[(size_t)(bm + ty*4 + i) * LL + bn + tx*4 + j] = acc[i][j] * 0.125f;
}

// ---------------------------------------------------------------------------
// Row softmax in place.  One block (256 thr) per row of 2048.
// ---------------------------------------------------------------------------
__global__ void __launch_bounds__(256) softmax_kernel(float* __restrict__ attn)
{
    float* row = attn + (size_t)blockIdx.x * LL;
    const int tid = threadIdx.x;
    __shared__ float red[32];

    float4 v0 = *(const float4*)&row[tid * 4];
    float4 v1 = *(const float4*)&row[1024 + tid * 4];
    float m = fmaxf(fmaxf(fmaxf(v0.x, v0.y), fmaxf(v0.z, v0.w)),
                    fmaxf(fmaxf(v1.x, v1.y), fmaxf(v1.z, v1.w)));
    #pragma unroll
    for (int o = 16; o; o >>= 1) m = fmaxf(m, __shfl_xor_sync(0xffffffffu, m, o));
    if ((tid & 31) == 0) red[tid >> 5] = m;
    __syncthreads();
    if (tid < 32) {
        float x = (tid < 8) ? red[tid] : -3.4e38f;
        #pragma unroll
        for (int o = 4; o; o >>= 1) x = fmaxf(x, __shfl_xor_sync(0xffffffffu, x, o));
        if (tid == 0) red[0] = x;
    }
    __syncthreads();
    m = red[0];
    __syncthreads();

    float e[8];
    e[0] = __expf(v0.x - m); e[1] = __expf(v0.y - m);
    e[2] = __expf(v0.z - m); e[3] = __expf(v0.w - m);
    e[4] = __expf(v1.x - m); e[5] = __expf(v1.y - m);
    e[6] = __expf(v1.z - m); e[7] = __expf(v1.w - m);
    float s = 0.f;
    #pragma unroll
    for (int i = 0; i < 8; i++) s += e[i];
    #pragma unroll
    for (int o = 16; o; o >>= 1) s += __shfl_xor_sync(0xffffffffu, s, o);
    if ((tid & 31) == 0) red[tid >> 5] = s;
    __syncthreads();
    if (tid < 32) {
        float x = (tid < 8) ? red[tid] : 0.f;
        #pragma unroll
        for (int o = 4; o; o >>= 1) x += __shfl_xor_sync(0xffffffffu, x, o);
        if (tid == 0) red[0] = x;
    }
    __syncthreads();
    float inv = 1.0f / red[0];

    float4 o0 = make_float4(e[0]*inv, e[1]*inv, e[2]*inv, e[3]*inv);
    float4 o1 = make_float4(e[4]*inv, e[5]*inv, e[6]*inv, e[7]*inv);
    *(float4*)&row[tid * 4] = o0;
    *(float4*)&row[1024 + tid * 4] = o1;
}

// ---------------------------------------------------------------------------
// Output: O[bh][2048,64] = P[bh][2048,2048] @ V[bh][2048,64]
// BM=64, BN=64(=DK), BK=16. grid (32 m-tiles, 32 bh).
// ---------------------------------------------------------------------------
__global__ void __launch_bounds__(256) out_kernel(const float* __restrict__ attn,
                                                  float* __restrict__ out)
{
    __shared__ float As[16][64];
    __shared__ float Bs[16][68];
    const int tid = threadIdx.x;
    const int tx = tid & 15, ty = tid >> 4;
    const int bh = blockIdx.y;
    const int b = bh >> 3, h = bh & 7;
    const float* __restrict__ P  = attn + (size_t)bh * LL * LL;
    const float* __restrict__ Vp = g_V + (size_t)b * LL * DM + h * DK;
    const int bm = blockIdx.x * 64;
    const int lm  = tid >> 2;
    const int lk  = (tid & 3) << 2;
    const int lkr = tid >> 4;
    const int lnq = (tid & 15) << 2;

    float acc[4][4] = {};
    for (int k0 = 0; k0 < LL; k0 += 16) {
        float4 a = *(const float4*)&P[(size_t)(bm + lm) * LL + k0 + lk];
        As[lk+0][lm] = a.x; As[lk+1][lm] = a.y; As[lk+2][lm] = a.z; As[lk+3][lm] = a.w;
        float4 v4 = *(const float4*)&Vp[(size_t)(k0 + lkr) * DM + lnq];
        *(float4*)&Bs[lkr][lnq] = v4;
        __syncthreads();
        #pragma unroll
        for (int k = 0; k < 16; k++) {
            float ar[4], br[4];
            #pragma unroll
            for (int i = 0; i < 4; i++) ar[i] = As[k][ty*4+i];
            #pragma unroll
            for (int j = 0; j < 4; j++) br[j] = Bs[k][tx*4+j];
            #pragma unroll
            for (int i = 0; i < 4; i++)
                #pragma unroll
                for (int j = 0; j < 4; j++)
                    acc[i][j] += ar[i] * br[j];
        }
        __syncthreads();
    }
    #pragma unroll
    for (int i = 0; i < 4; i++)
        #pragma unroll
        for (int j = 0; j < 4; j++)
            out[(size_t)(b * LL + bm + ty*4 + i) * DM + h * DK + tx*4 + j] = acc[i][j];
}

// ---------------------------------------------------------------------------
extern "C" void kernel_launch(void* const* d_in, const int* in_sizes, int n_in,
                              void* d_out, int out_size)
{
    const float* q  = (const float*)d_in[0];
    const float* k  = (const float*)d_in[1];
    const float* v  = (const float*)d_in[2];
    const float* Wq = (const float*)d_in[3];
    const float* bq = (const float*)d_in[4];
    const float* Wk = (const float*)d_in[5];
    const float* bk = (const float*)d_in[6];
    const float* Wv = (const float*)d_in[7];
    const float* bv = (const float*)d_in[8];

    float* out  = (float*)d_out;
    float* attn = out + OUT_ELEMS;

    float *gQ, *gK, *gV;
    cudaGetSymbolAddress((void**)&gQ, g_Q);
    cudaGetSymbolAddress((void**)&gK, g_K);
    cudaGetSymbolAddress((void**)&gV, g_V);

    dim3 blk(256);
    proj_kernel<<<dim3(8, 128), blk>>>(q, Wq, bq, gQ);
    proj_kernel<<<dim3(8, 128), blk>>>(k, Wk, bk, gK);
    proj_kernel<<<dim3(8, 128), blk>>>(v, Wv, bv, gV);
    scores_kernel<<<dim3(32, 32, 32), blk>>>(attn);
    softmax_kernel<<<BB * NH * LL, blk>>>(attn);
    out_kernel<<<dim3(32, 32), blk>>>(attn, out);
}

// round 4
// speedup vs baseline: 1.3135x; 1.3128x over previous
#include <cuda_runtime.h>

#define DM 512
#define NH 8
#define DK 64
#define BB 4
#define LL 2048
#define MROWS (BB*LL)                    // 8192
#define OUT_ELEMS ((size_t)MROWS*DM)     // 4,194,304
#define NROWS (BB*NH*LL)                 // 65536 softmax rows
#define NCT 16                           // 2048 / 128 col tiles

__device__ float g_Q[MROWS*DM];
__device__ float g_K[MROWS*DM];
__device__ float g_V[MROWS*DM];
__device__ float g_mpart[(size_t)NROWS*NCT];
__device__ float g_spart[(size_t)NROWS*NCT];
__device__ float g_rowm[NROWS];
__device__ float g_rowinv[NROWS];

struct ProjArgs {
    const float* X[3];
    const float* W[3];
    const float* b[3];
    float*       Y[3];
};

// ---------------------------------------------------------------------------
// Fused projections: Y[z] = X[z] @ W[z] + b[z].  128x128 tile, 8x8 micro.
// grid (N/128=4, M/128=64, 3), 256 threads.
// ---------------------------------------------------------------------------
__global__ void __launch_bounds__(256) proj128_kernel(ProjArgs args)
{
    const int z = blockIdx.z;
    const float* __restrict__ X    = args.X[z];
    const float* __restrict__ W    = args.W[z];
    const float* __restrict__ bias = args.b[z];
    float* __restrict__ Y          = args.Y[z];

    __shared__ float As[16][132];
    __shared__ float Bs[16][128];

    const int tid = threadIdx.x;
    const int tx = tid & 15, ty = tid >> 4;
    const int bm = blockIdx.y * 128, bn = blockIdx.x * 128;

    const int arow = tid >> 2;          // 0..63
    const int akq  = (tid & 3) << 2;    // 0,4,8,12
    const int brow = tid >> 5;          // 0..7
    const int bcol = (tid & 31) << 2;   // 0..124

    float acc[8][8] = {};

    for (int k0 = 0; k0 < 512; k0 += 16) {
        float4 a0 = *(const float4*)&X[(size_t)(bm + arow)      * 512 + k0 + akq];
        float4 a1 = *(const float4*)&X[(size_t)(bm + arow + 64) * 512 + k0 + akq];
        float4 b0 = *(const float4*)&W[(size_t)(k0 + brow)      * 512 + bn + bcol];
        float4 b1 = *(const float4*)&W[(size_t)(k0 + brow + 8)  * 512 + bn + bcol];
        __syncthreads();
        As[akq+0][arow] = a0.x; As[akq+1][arow] = a0.y;
        As[akq+2][arow] = a0.z; As[akq+3][arow] = a0.w;
        As[akq+0][arow+64] = a1.x; As[akq+1][arow+64] = a1.y;
        As[akq+2][arow+64] = a1.z; As[akq+3][arow+64] = a1.w;
        *(float4*)&Bs[brow][bcol]   = b0;
        *(float4*)&Bs[brow+8][bcol] = b1;
        __syncthreads();
        #pragma unroll
        for (int k = 0; k < 16; k++) {
            float4 av0 = *(float4*)&As[k][ty*4];
            float4 av1 = *(float4*)&As[k][64 + ty*4];
            float4 bv0 = *(float4*)&Bs[k][tx*4];
            float4 bv1 = *(float4*)&Bs[k][64 + tx*4];
            float ar[8] = {av0.x,av0.y,av0.z,av0.w,av1.x,av1.y,av1.z,av1.w};
            float br[8] = {bv0.x,bv0.y,bv0.z,bv0.w,bv1.x,bv1.y,bv1.z,bv1.w};
            #pragma unroll
            for (int i = 0; i < 8; i++)
                #pragma unroll
                for (int j = 0; j < 8; j++)
                    acc[i][j] += ar[i] * br[j];
        }
    }

    #pragma unroll
    for (int i = 0; i < 8; i++) {
        int r = bm + ((i < 4) ? (ty*4 + i) : (64 + ty*4 + i - 4));
        #pragma unroll
        for (int jq = 0; jq < 2; jq++) {
            int c = bn + jq*64 + tx*4;
            float4 o;
            o.x = acc[i][jq*4+0] + bias[c+0];
            o.y = acc[i][jq*4+1] + bias[c+1];
            o.z = acc[i][jq*4+2] + bias[c+2];
            o.w = acc[i][jq*4+3] + bias[c+3];
            *(float4*)&Y[(size_t)r * 512 + c] = o;
        }
    }
}

// ---------------------------------------------------------------------------
// Scores + partial softmax stats.  S = Q K^T / 8 written raw to attn region.
// 128x128 tile, 8x8 micro, K=64.  Per (row, coltile) partial max / sumexp.
// grid (16, 16, 32), 256 threads.
// ---------------------------------------------------------------------------
__global__ void __launch_bounds__(256) scores128_kernel(float* __restrict__ attn)
{
    __shared__ float As[16][132];
    __shared__ float Bs[16][132];

    const int tid = threadIdx.x;
    const int tx = tid & 15, ty = tid >> 4;
    const int bh = blockIdx.z;
    const int b = bh >> 3, h = bh & 7;
    const float* __restrict__ Qp = g_Q + (size_t)b * LL * DM + h * DK;
    const float* __restrict__ Kp = g_K + (size_t)b * LL * DM + h * DK;
    const int bm = blockIdx.y * 128, bn = blockIdx.x * 128;

    const int arow = tid >> 2;
    const int akq  = (tid & 3) << 2;

    float acc[8][8] = {};

    for (int k0 = 0; k0 < 64; k0 += 16) {
        float4 a0 = *(const float4*)&Qp[(size_t)(bm + arow)      * DM + k0 + akq];
        float4 a1 = *(const float4*)&Qp[(size_t)(bm + arow + 64) * DM + k0 + akq];
        float4 c0 = *(const float4*)&Kp[(size_t)(bn + arow)      * DM + k0 + akq];
        float4 c1 = *(const float4*)&Kp[(size_t)(bn + arow + 64) * DM + k0 + akq];
        __syncthreads();
        As[akq+0][arow] = a0.x; As[akq+1][arow] = a0.y;
        As[akq+2][arow] = a0.z; As[akq+3][arow] = a0.w;
        As[akq+0][arow+64] = a1.x; As[akq+1][arow+64] = a1.y;
        As[akq+2][arow+64] = a1.z; As[akq+3][arow+64] = a1.w;
        Bs[akq+0][arow] = c0.x; Bs[akq+1][arow] = c0.y;
        Bs[akq+2][arow] = c0.z; Bs[akq+3][arow] = c0.w;
        Bs[akq+0][arow+64] = c1.x; Bs[akq+1][arow+64] = c1.y;
        Bs[akq+2][arow+64] = c1.z; Bs[akq+3][arow+64] = c1.w;
        __syncthreads();
        #pragma unroll
        for (int k = 0; k < 16; k++) {
            float4 av0 = *(float4*)&As[k][ty*4];
            float4 av1 = *(float4*)&As[k][64 + ty*4];
            float4 bv0 = *(float4*)&Bs[k][tx*4];
            float4 bv1 = *(float4*)&Bs[k][64 + tx*4];
            float ar[8] = {av0.x,av0.y,av0.z,av0.w,av1.x,av1.y,av1.z,av1.w};
            float br[8] = {bv0.x,bv0.y,bv0.z,bv0.w,bv1.x,bv1.y,bv1.z,bv1.w};
            #pragma unroll
            for (int i = 0; i < 8; i++)
                #pragma unroll
                for (int j = 0; j < 8; j++)
                    acc[i][j] += ar[i] * br[j];
        }
    }

    // scale
    #pragma unroll
    for (int i = 0; i < 8; i++)
        #pragma unroll
        for (int j = 0; j < 8; j++)
            acc[i][j] *= 0.125f;

    // write raw S tile
    float* S = attn + (size_t)bh * LL * LL;
    #pragma unroll
    for (int i = 0; i < 8; i++) {
        int r = bm + ((i < 4) ? (ty*4 + i) : (64 + ty*4 + i - 4));
        #pragma unroll
        for (int jq = 0; jq < 2; jq++) {
            int c = bn + jq*64 + tx*4;
            float4 o = make_float4(acc[i][jq*4+0], acc[i][jq*4+1],
                                   acc[i][jq*4+2], acc[i][jq*4+3]);
            *(float4*)&S[(size_t)r * LL + c] = o;
        }
    }

    // per-row partial stats over this 128-wide tile.
    // lanes with same ty share a 16-lane group (tx) -> shfl_xor 1,2,4,8.
    float mv[8], sv[8];
    #pragma unroll
    for (int i = 0; i < 8; i++) {
        float m = acc[i][0];
        #pragma unroll
        for (int j = 1; j < 8; j++) m = fmaxf(m, acc[i][j]);
        #pragma unroll
        for (int o = 1; o < 16; o <<= 1)
            m = fmaxf(m, __shfl_xor_sync(0xffffffffu, m, o));
        mv[i] = m;
        float s = 0.f;
        #pragma unroll
        for (int j = 0; j < 8; j++) s += __expf(acc[i][j] - m);
        #pragma unroll
        for (int o = 1; o < 16; o <<= 1)
            s += __shfl_xor_sync(0xffffffffu, s, o);
        sv[i] = s;
    }
    if (tx == 0) {
        const int ct = blockIdx.x;
        #pragma unroll
        for (int i = 0; i < 8; i++) {
            int r = bm + ((i < 4) ? (ty*4 + i) : (64 + ty*4 + i - 4));
            size_t idx = (size_t)(bh * LL + r) * NCT + ct;
            g_mpart[idx] = mv[i];
            g_spart[idx] = sv[i];
        }
    }
}

// ---------------------------------------------------------------------------
// Combine partial stats -> per-row max and 1/sum.
// ---------------------------------------------------------------------------
__global__ void __launch_bounds__(256) combine_kernel()
{
    int row = blockIdx.x * 256 + threadIdx.x;   // 0..NROWS-1
    const float* mp = &g_mpart[(size_t)row * NCT];
    const float* sp = &g_spart[(size_t)row * NCT];
    float m = mp[0];
    #pragma unroll
    for (int t = 1; t < NCT; t++) m = fmaxf(m, mp[t]);
    float s = 0.f;
    #pragma unroll
    for (int t = 0; t < NCT; t++) s += sp[t] * __expf(mp[t] - m);
    g_rowm[row] = m;
    g_rowinv[row] = 1.0f / s;
}

// ---------------------------------------------------------------------------
// Normalize + write P (in place over raw S) + O = P @ V.
// BM=128, BN=64, BK=32, 8x4 micro.  grid (16, 32), 256 threads.
// ---------------------------------------------------------------------------
__global__ void __launch_bounds__(256) av128_kernel(float* __restrict__ attn,
                                                    float* __restrict__ out)
{
    __shared__ float As[32][132];
    __shared__ float Bs[32][64];

    const int tid = threadIdx.x;
    const int tx = tid & 15, ty = tid >> 4;
    const int bh = blockIdx.y;
    const int b = bh >> 3, h = bh & 7;
    const int bm = blockIdx.x * 128;
    float* __restrict__ S = attn + (size_t)bh * LL * LL;
    const float* __restrict__ Vp = g_V + (size_t)b * LL * DM + h * DK;

    const int srow = tid >> 1;            // 0..127 (one S row per thread)
    const int scb  = (tid & 1) << 4;      // 0 or 16
    const int vrow = tid >> 3;            // 0..31
    const int vcol = (tid & 7) << 3;      // 0..56

    const float m_s = g_rowm[bh * LL + bm + srow];
    const float i_s = g_rowinv[bh * LL + bm + srow];

    float acc[8][4] = {};

    for (int k0 = 0; k0 < LL; k0 += 32) {
        float4 sv[4];
        #pragma unroll
        for (int q = 0; q < 4; q++) {
            float4 v = *(const float4*)&S[(size_t)(bm + srow) * LL + k0 + scb + q*4];
            v.x = __expf(v.x - m_s) * i_s;
            v.y = __expf(v.y - m_s) * i_s;
            v.z = __expf(v.z - m_s) * i_s;
            v.w = __expf(v.w - m_s) * i_s;
            sv[q] = v;
        }
        float4 v0 = *(const float4*)&Vp[(size_t)(k0 + vrow) * DM + vcol];
        float4 v1 = *(const float4*)&Vp[(size_t)(k0 + vrow) * DM + vcol + 4];
        __syncthreads();
        #pragma unroll
        for (int q = 0; q < 4; q++) {
            As[scb + q*4 + 0][srow] = sv[q].x;
            As[scb + q*4 + 1][srow] = sv[q].y;
            As[scb + q*4 + 2][srow] = sv[q].z;
            As[scb + q*4 + 3][srow] = sv[q].w;
        }
        *(float4*)&Bs[vrow][vcol]     = v0;
        *(float4*)&Bs[vrow][vcol + 4] = v1;
        __syncthreads();
        // overlap: write normalized P back to gmem while computing
        #pragma unroll
        for (int q = 0; q < 4; q++)
            *(float4*)&S[(size_t)(bm + srow) * LL + k0 + scb + q*4] = sv[q];
        #pragma unroll
        for (int k = 0; k < 32; k++) {
            float4 av0 = *(float4*)&As[k][ty*4];
            float4 av1 = *(float4*)&As[k][64 + ty*4];
            float4 bv  = *(float4*)&Bs[k][tx*4];
            float ar[8] = {av0.x,av0.y,av0.z,av0.w,av1.x,av1.y,av1.z,av1.w};
            float br[4] = {bv.x,bv.y,bv.z,bv.w};
            #pragma unroll
            for (int i = 0; i < 8; i++)
                #pragma unroll
                for (int j = 0; j < 4; j++)
                    acc[i][j] += ar[i] * br[j];
        }
    }

    #pragma unroll
    for (int i = 0; i < 8; i++) {
        int r = bm + ((i < 4) ? (ty*4 + i) : (64 + ty*4 + i - 4));
        float4 o = make_float4(acc[i][0], acc[i][1], acc[i][2], acc[i][3]);
        *(float4*)&out[(size_t)(b * LL + r) * DM + h * DK + tx*4] = o;
    }
}

// ---------------------------------------------------------------------------
extern "C" void kernel_launch(void* const* d_in, const int* in_sizes, int n_in,
                              void* d_out, int out_size)
{
    const float* q  = (const float*)d_in[0];
    const float* k  = (const float*)d_in[1];
    const float* v  = (const float*)d_in[2];
    const float* Wq = (const float*)d_in[3];
    const float* bq = (const float*)d_in[4];
    const float* Wk = (const float*)d_in[5];
    const float* bk = (const float*)d_in[6];
    const float* Wv = (const float*)d_in[7];
    const float* bv = (const float*)d_in[8];

    float* out  = (float*)d_out;
    float* attn = out + OUT_ELEMS;

    float *gQ, *gK, *gV;
    cudaGetSymbolAddress((void**)&gQ, g_Q);
    cudaGetSymbolAddress((void**)&gK, g_K);
    cudaGetSymbolAddress((void**)&gV, g_V);

    ProjArgs pa;
    pa.X[0] = q;  pa.X[1] = k;  pa.X[2] = v;
    pa.W[0] = Wq; pa.W[1] = Wk; pa.W[2] = Wv;
    pa.b[0] = bq; pa.b[1] = bk; pa.b[2] = bv;
    pa.Y[0] = gQ; pa.Y[1] = gK; pa.Y[2] = gV;

    dim3 blk(256);
    proj128_kernel<<<dim3(4, 64, 3), blk>>>(pa);
    scores128_kernel<<<dim3(16, 16, 32), blk>>>(attn);
    combine_kernel<<<dim3(NROWS / 256), blk>>>();
    av128_kernel<<<dim3(16, 32), blk>>>(attn, out);
}

// round 5
// speedup vs baseline: 1.3148x; 1.0010x over previous
#include <cuda_runtime.h>

#define DM 512
#define NH 8
#define DK 64
#define BB 4
#define LL 2048
#define MROWS (BB*LL)                    // 8192
#define OUT_ELEMS ((size_t)MROWS*DM)     // 4,194,304
#define NROWS (BB*NH*LL)                 // 65536 softmax rows
#define NCT 16                           // 2048 / 128 col tiles

__device__ float g_Q[MROWS*DM];
__device__ float g_K[MROWS*DM];
__device__ float g_V[MROWS*DM];
__device__ float g_mpart[(size_t)NROWS*NCT];
__device__ float g_spart[(size_t)NROWS*NCT];
__device__ float g_rowm[NROWS];
__device__ float g_rowinv[NROWS];

struct ProjArgs {
    const float* X[3];
    const float* W[3];
    const float* b[3];
    float*       Y[3];
};

// ---------------------------------------------------------------------------
// Fused projections: Y[z] = X[z] @ W[z] + b[z].  128x128 tile, 8x8 micro.
// grid (N/128=4, M/128=64, 3), 256 threads.
// ---------------------------------------------------------------------------
__global__ void __launch_bounds__(256) proj128_kernel(ProjArgs args)
{
    const int z = blockIdx.z;
    const float* __restrict__ X    = args.X[z];
    const float* __restrict__ W    = args.W[z];
    const float* __restrict__ bias = args.b[z];
    float* __restrict__ Y          = args.Y[z];

    __shared__ float As[16][132];
    __shared__ float Bs[16][128];

    const int tid = threadIdx.x;
    const int tx = tid & 15, ty = tid >> 4;
    const int bm = blockIdx.y * 128, bn = blockIdx.x * 128;

    const int arow = tid >> 2;          // 0..63
    const int akq  = (tid & 3) << 2;    // 0,4,8,12
    const int brow = tid >> 5;          // 0..7
    const int bcol = (tid & 31) << 2;   // 0..124

    float acc[8][8] = {};

    for (int k0 = 0; k0 < 512; k0 += 16) {
        float4 a0 = *(const float4*)&X[(size_t)(bm + arow)      * 512 + k0 + akq];
        float4 a1 = *(const float4*)&X[(size_t)(bm + arow + 64) * 512 + k0 + akq];
        float4 b0 = *(const float4*)&W[(size_t)(k0 + brow)      * 512 + bn + bcol];
        float4 b1 = *(const float4*)&W[(size_t)(k0 + brow + 8)  * 512 + bn + bcol];
        __syncthreads();
        As[akq+0][arow] = a0.x; As[akq+1][arow] = a0.y;
        As[akq+2][arow] = a0.z; As[akq+3][arow] = a0.w;
        As[akq+0][arow+64] = a1.x; As[akq+1][arow+64] = a1.y;
        As[akq+2][arow+64] = a1.z; As[akq+3][arow+64] = a1.w;
        *(float4*)&Bs[brow][bcol]   = b0;
        *(float4*)&Bs[brow+8][bcol] = b1;
        __syncthreads();
        #pragma unroll
        for (int k = 0; k < 16; k++) {
            float4 av0 = *(float4*)&As[k][ty*4];
            float4 av1 = *(float4*)&As[k][64 + ty*4];
            float4 bv0 = *(float4*)&Bs[k][tx*4];
            float4 bv1 = *(float4*)&Bs[k][64 + tx*4];
            float ar[8] = {av0.x,av0.y,av0.z,av0.w,av1.x,av1.y,av1.z,av1.w};
            float br[8] = {bv0.x,bv0.y,bv0.z,bv0.w,bv1.x,bv1.y,bv1.z,bv1.w};
            #pragma unroll
            for (int i = 0; i < 8; i++)
                #pragma unroll
                for (int j = 0; j < 8; j++)
                    acc[i][j] += ar[i] * br[j];
        }
    }

    #pragma unroll
    for (int i = 0; i < 8; i++) {
        int r = bm + ((i < 4) ? (ty*4 + i) : (64 + ty*4 + i - 4));
        #pragma unroll
        for (int jq = 0; jq < 2; jq++) {
            int c = bn + jq*64 + tx*4;
            float4 o;
            o.x = acc[i][jq*4+0] + bias[c+0];
            o.y = acc[i][jq*4+1] + bias[c+1];
            o.z = acc[i][jq*4+2] + bias[c+2];
            o.w = acc[i][jq*4+3] + bias[c+3];
            *(float4*)&Y[(size_t)r * 512 + c] = o;
        }
    }
}

// ---------------------------------------------------------------------------
// Scores + partial softmax stats.  S = Q K^T / 8 written raw to attn region.
// 128x128 tile, 8x8 micro, K=64.  Per (row, coltile) partial max / sumexp.
// grid (16, 16, 32), 256 threads.
// ---------------------------------------------------------------------------
__global__ void __launch_bounds__(256) scores128_kernel(float* __restrict__ attn)
{
    __shared__ float As[16][132];
    __shared__ float Bs[16][132];

    const int tid = threadIdx.x;
    const int tx = tid & 15, ty = tid >> 4;
    const int bh = blockIdx.z;
    const int b = bh >> 3, h = bh & 7;
    const float* __restrict__ Qp = g_Q + (size_t)b * LL * DM + h * DK;
    const float* __restrict__ Kp = g_K + (size_t)b * LL * DM + h * DK;
    const int bm = blockIdx.y * 128, bn = blockIdx.x * 128;

    const int arow = tid >> 2;
    const int akq  = (tid & 3) << 2;

    float acc[8][8] = {};

    for (int k0 = 0; k0 < 64; k0 += 16) {
        float4 a0 = *(const float4*)&Qp[(size_t)(bm + arow)      * DM + k0 + akq];
        float4 a1 = *(const float4*)&Qp[(size_t)(bm + arow + 64) * DM + k0 + akq];
        float4 c0 = *(const float4*)&Kp[(size_t)(bn + arow)      * DM + k0 + akq];
        float4 c1 = *(const float4*)&Kp[(size_t)(bn + arow + 64) * DM + k0 + akq];
        __syncthreads();
        As[akq+0][arow] = a0.x; As[akq+1][arow] = a0.y;
        As[akq+2][arow] = a0.z; As[akq+3][arow] = a0.w;
        As[akq+0][arow+64] = a1.x; As[akq+1][arow+64] = a1.y;
        As[akq+2][arow+64] = a1.z; As[akq+3][arow+64] = a1.w;
        Bs[akq+0][arow] = c0.x; Bs[akq+1][arow] = c0.y;
        Bs[akq+2][arow] = c0.z; Bs[akq+3][arow] = c0.w;
        Bs[akq+0][arow+64] = c1.x; Bs[akq+1][arow+64] = c1.y;
        Bs[akq+2][arow+64] = c1.z; Bs[akq+3][arow+64] = c1.w;
        __syncthreads();
        #pragma unroll
        for (int k = 0; k < 16; k++) {
            float4 av0 = *(float4*)&As[k][ty*4];
            float4 av1 = *(float4*)&As[k][64 + ty*4];
            float4 bv0 = *(float4*)&Bs[k][tx*4];
            float4 bv1 = *(float4*)&Bs[k][64 + tx*4];
            float ar[8] = {av0.x,av0.y,av0.z,av0.w,av1.x,av1.y,av1.z,av1.w};
            float br[8] = {bv0.x,bv0.y,bv0.z,bv0.w,bv1.x,bv1.y,bv1.z,bv1.w};
            #pragma unroll
            for (int i = 0; i < 8; i++)
                #pragma unroll
                for (int j = 0; j < 8; j++)
                    acc[i][j] += ar[i] * br[j];
        }
    }

    // scale
    #pragma unroll
    for (int i = 0; i < 8; i++)
        #pragma unroll
        for (int j = 0; j < 8; j++)
            acc[i][j] *= 0.125f;

    // write raw S tile
    float* S = attn + (size_t)bh * LL * LL;
    #pragma unroll
    for (int i = 0; i < 8; i++) {
        int r = bm + ((i < 4) ? (ty*4 + i) : (64 + ty*4 + i - 4));
        #pragma unroll
        for (int jq = 0; jq < 2; jq++) {
            int c = bn + jq*64 + tx*4;
            float4 o = make_float4(acc[i][jq*4+0], acc[i][jq*4+1],
                                   acc[i][jq*4+2], acc[i][jq*4+3]);
            *(float4*)&S[(size_t)r * LL + c] = o;
        }
    }

    // per-row partial stats over this 128-wide tile.
    // lanes with same ty share a 16-lane group (tx) -> shfl_xor 1,2,4,8.
    float mv[8], sv[8];
    #pragma unroll
    for (int i = 0; i < 8; i++) {
        float m = acc[i][0];
        #pragma unroll
        for (int j = 1; j < 8; j++) m = fmaxf(m, acc[i][j]);
        #pragma unroll
        for (int o = 1; o < 16; o <<= 1)
            m = fmaxf(m, __shfl_xor_sync(0xffffffffu, m, o));
        mv[i] = m;
        float s = 0.f;
        #pragma unroll
        for (int j = 0; j < 8; j++) s += __expf(acc[i][j] - m);
        #pragma unroll
        for (int o = 1; o < 16; o <<= 1)
            s += __shfl_xor_sync(0xffffffffu, s, o);
        sv[i] = s;
    }
    if (tx == 0) {
        const int ct = blockIdx.x;
        #pragma unroll
        for (int i = 0; i < 8; i++) {
            int r = bm + ((i < 4) ? (ty*4 + i) : (64 + ty*4 + i - 4));
            size_t idx = (size_t)(bh * LL + r) * NCT + ct;
            g_mpart[idx] = mv[i];
            g_spart[idx] = sv[i];
        }
    }
}

// ---------------------------------------------------------------------------
// Combine partial stats -> per-row max and 1/sum.
// ---------------------------------------------------------------------------
__global__ void __launch_bounds__(256) combine_kernel()
{
    int row = blockIdx.x * 256 + threadIdx.x;   // 0..NROWS-1
    const float* mp = &g_mpart[(size_t)row * NCT];
    const float* sp = &g_spart[(size_t)row * NCT];
    float m = mp[0];
    #pragma unroll
    for (int t = 1; t < NCT; t++) m = fmaxf(m, mp[t]);
    float s = 0.f;
    #pragma unroll
    for (int t = 0; t < NCT; t++) s += sp[t] * __expf(mp[t] - m);
    g_rowm[row] = m;
    g_rowinv[row] = 1.0f / s;
}

// ---------------------------------------------------------------------------
// Normalize + write P (in place over raw S) + O = P @ V.
// BM=128, BN=64, BK=32, 8x4 micro.  grid (16, 32), 256 threads.
// ---------------------------------------------------------------------------
__global__ void __launch_bounds__(256) av128_kernel(float* __restrict__ attn,
                                                    float* __restrict__ out)
{
    __shared__ float As[32][132];
    __shared__ float Bs[32][64];

    const int tid = threadIdx.x;
    const int tx = tid & 15, ty = tid >> 4;
    const int bh = blockIdx.y;
    const int b = bh >> 3, h = bh & 7;
    const int bm = blockIdx.x * 128;
    float* __restrict__ S = attn + (size_t)bh * LL * LL;
    const float* __restrict__ Vp = g_V + (size_t)b * LL * DM + h * DK;

    const int srow = tid >> 1;            // 0..127 (one S row per thread)
    const int scb  = (tid & 1) << 4;      // 0 or 16
    const int vrow = tid >> 3;            // 0..31
    const int vcol = (tid & 7) << 3;      // 0..56

    const float m_s = g_rowm[bh * LL + bm + srow];
    const float i_s = g_rowinv[bh * LL + bm + srow];

    float acc[8][4] = {};

    for (int k0 = 0; k0 < LL; k0 += 32) {
        float4 sv[4];
        #pragma unroll
        for (int q = 0; q < 4; q++) {
            float4 v = *(const float4*)&S[(size_t)(bm + srow) * LL + k0 + scb + q*4];
            v.x = __expf(v.x - m_s) * i_s;
            v.y = __expf(v.y - m_s) * i_s;
            v.z = __expf(v.z - m_s) * i_s;
            v.w = __expf(v.w - m_s) * i_s;
            sv[q] = v;
        }
        float4 v0 = *(const float4*)&Vp[(size_t)(k0 + vrow) * DM + vcol];
        float4 v1 = *(const float4*)&Vp[(size_t)(k0 + vrow) * DM + vcol + 4];
        __syncthreads();
        #pragma unroll
        for (int q = 0; q < 4; q++) {
            As[scb + q*4 + 0][srow] = sv[q].x;
            As[scb + q*4 + 1][srow] = sv[q].y;
            As[scb + q*4 + 2][srow] = sv[q].z;
            As[scb + q*4 + 3][srow] = sv[q].w;
        }
        *(float4*)&Bs[vrow][vcol]     = v0;
        *(float4*)&Bs[vrow][vcol + 4] = v1;
        __syncthreads();
        // overlap: write normalized P back to gmem while computing
        #pragma unroll
        for (int q = 0; q < 4; q++)
            *(float4*)&S[(size_t)(bm + srow) * LL + k0 + scb + q*4] = sv[q];
        #pragma unroll
        for (int k = 0; k < 32; k++) {
            float4 av0 = *(float4*)&As[k][ty*4];
            float4 av1 = *(float4*)&As[k][64 + ty*4];
            float4 bv  = *(float4*)&Bs[k][tx*4];
            float ar[8] = {av0.x,av0.y,av0.z,av0.w,av1.x,av1.y,av1.z,av1.w};
            float br[4] = {bv.x,bv.y,bv.z,bv.w};
            #pragma unroll
            for (int i = 0; i < 8; i++)
                #pragma unroll
                for (int j = 0; j < 4; j++)
                    acc[i][j] += ar[i] * br[j];
        }
    }

    #pragma unroll
    for (int i = 0; i < 8; i++) {
        int r = bm + ((i < 4) ? (ty*4 + i) : (64 + ty*4 + i - 4));
        float4 o = make_float4(acc[i][0], acc[i][1], acc[i][2], acc[i][3]);
        *(float4*)&out[(size_t)(b * LL + r) * DM + h * DK + tx*4] = o;
    }
}

// ---------------------------------------------------------------------------
extern "C" void kernel_launch(void* const* d_in, const int* in_sizes, int n_in,
                              void* d_out, int out_size)
{
    const float* q  = (const float*)d_in[0];
    const float* k  = (const float*)d_in[1];
    const float* v  = (const float*)d_in[2];
    const float* Wq = (const float*)d_in[3];
    const float* bq = (const float*)d_in[4];
    const float* Wk = (const float*)d_in[5];
    const float* bk = (const float*)d_in[6];
    const float* Wv = (const float*)d_in[7];
    const float* bv = (const float*)d_in[8];

    float* out  = (float*)d_out;
    float* attn = out + OUT_ELEMS;

    float *gQ, *gK, *gV;
    cudaGetSymbolAddress((void**)&gQ, g_Q);
    cudaGetSymbolAddress((void**)&gK, g_K);
    cudaGetSymbolAddress((void**)&gV, g_V);

    ProjArgs pa;
    pa.X[0] = q;  pa.X[1] = k;  pa.X[2] = v;
    pa.W[0] = Wq; pa.W[1] = Wk; pa.W[2] = Wv;
    pa.b[0] = bq; pa.b[1] = bk; pa.b[2] = bv;
    pa.Y[0] = gQ; pa.Y[1] = gK; pa.Y[2] = gV;

    dim3 blk(256);
    proj128_kernel<<<dim3(4, 64, 3), blk>>>(pa);
    scores128_kernel<<<dim3(16, 16, 32), blk>>>(attn);
    combine_kernel<<<dim3(NROWS / 256), blk>>>();
    av128_kernel<<<dim3(16, 32), blk>>>(attn, out);
}